// round 3
// baseline (speedup 1.0000x reference)
#include <cuda_runtime.h>
#include <cuda_bf16.h>
#include <math.h>

// ---------------------------------------------------------------------------
// VS_DiT_Block: B=4, N=1024, D=1024, H=16, HD=64, S=77, DF=4096
// fp32: double-buffered SGEMM (128x128x8, 8x8/thread) with fused
// bias/GELU/gated-residual epilogues + tiled attention.
// ---------------------------------------------------------------------------

#define Bv 4
#define Nv 1024
#define Dv 1024
#define Hv 16
#define HDv 64
#define Sv 77
#define DFv 4096
#define ATT_SCALE 0.125f

// epilogue codes
#define EPI_NONE 0
#define EPI_GELU 1

// -------------------------- device scratch (no malloc allowed) -------------
__device__ float g_ts[Bv * Dv];                       // silu(t_emb)
__device__ float g_mod[Bv * 6 * Dv];                  // ada modulation
__device__ float g_xm1[Bv * Nv * Dv];
__device__ float g_qkv[Bv * Nv * 3 * Dv];
__device__ float g_scores[(size_t)Bv * Hv * Nv * Nv]; // 256 MB
__device__ float g_sa[Bv * Nv * Dv];
__device__ float g_x1[Bv * Nv * Dv];
__device__ float g_xn2[Bv * Nv * Dv];
__device__ float g_qc[Bv * Nv * Dv];
__device__ float g_kvc[Bv * Sv * 2 * Dv];
__device__ float g_cs[(size_t)Bv * Hv * Nv * Sv];
__device__ float g_ca[Bv * Nv * Dv];
__device__ float g_x2[Bv * Nv * Dv];
__device__ float g_xm3[Bv * Nv * Dv];
__device__ float g_h[Bv * Nv * DFv];

// -------------------------- reduction helpers ------------------------------
__device__ __forceinline__ float warpReduceSum(float v) {
    #pragma unroll
    for (int o = 16; o > 0; o >>= 1) v += __shfl_xor_sync(0xffffffffu, v, o);
    return v;
}
__device__ __forceinline__ float warpReduceMax(float v) {
    #pragma unroll
    for (int o = 16; o > 0; o >>= 1) v = fmaxf(v, __shfl_xor_sync(0xffffffffu, v, o));
    return v;
}
__device__ __forceinline__ float blockReduceSum(float v, float* sm) {
    int w = threadIdx.x >> 5, l = threadIdx.x & 31;
    v = warpReduceSum(v);
    if (l == 0) sm[w] = v;
    __syncthreads();
    int nw = blockDim.x >> 5;
    float r = 0.f;
    for (int i = 0; i < nw; i++) r += sm[i];
    __syncthreads();
    return r;
}
__device__ __forceinline__ float blockReduceMax(float v, float* sm) {
    int w = threadIdx.x >> 5, l = threadIdx.x & 31;
    v = warpReduceMax(v);
    if (l == 0) sm[w] = v;
    __syncthreads();
    int nw = blockDim.x >> 5;
    float r = -INFINITY;
    for (int i = 0; i < nw; i++) r = fmaxf(r, sm[i]);
    __syncthreads();
    return r;
}

// -------------------------- pointwise kernels ------------------------------
__global__ void silu_kernel(const float* __restrict__ t, float* __restrict__ out) {
    int i = blockIdx.x * 256 + threadIdx.x;
    if (i < Bv * Dv) {
        float v = t[i];
        out[i] = v / (1.f + __expf(-v));
    }
}

// mod = silu(t) @ ada_w + ada_b : (4 x 1024) @ (1024 x 6144)
__global__ __launch_bounds__(256) void mod_gemm_kernel(
    const float* __restrict__ ts, const float* __restrict__ ada_w,
    const float* __restrict__ ada_b, float* __restrict__ mod) {
    __shared__ float s_ts[Bv][Dv];
    int tid = threadIdx.x;
    for (int i = tid; i < Bv * Dv; i += 256) s_ts[i >> 10][i & 1023] = ts[i];
    __syncthreads();
    int col = blockIdx.x * 256 + tid;
    float a0 = 0.f, a1 = 0.f, a2 = 0.f, a3 = 0.f;
    #pragma unroll 4
    for (int k = 0; k < Dv; k++) {
        float w = ada_w[(size_t)k * (6 * Dv) + col];
        a0 += s_ts[0][k] * w;
        a1 += s_ts[1][k] * w;
        a2 += s_ts[2][k] * w;
        a3 += s_ts[3][k] * w;
    }
    float bb = ada_b[col];
    mod[0 * 6 * Dv + col] = a0 + bb;
    mod[1 * 6 * Dv + col] = a1 + bb;
    mod[2 * 6 * Dv + col] = a2 + bb;
    mod[3 * 6 * Dv + col] = a3 + bb;
}

// LayerNorm (+ optional shift/scale modulation). One block per row of 1024.
__global__ __launch_bounds__(256) void ln_kernel(
    const float* __restrict__ x, const float* __restrict__ mod,
    int shift_chunk, float* __restrict__ out) {
    __shared__ float sm[8];
    int row = blockIdx.x;
    int b = row >> 10;
    const float4* xr = (const float4*)(x + (size_t)row * Dv);
    float4 v = xr[threadIdx.x];
    float mean = blockReduceSum(v.x + v.y + v.z + v.w, sm) * (1.f / 1024.f);
    float d0 = v.x - mean, d1 = v.y - mean, d2 = v.z - mean, d3 = v.w - mean;
    float var = blockReduceSum(d0 * d0 + d1 * d1 + d2 * d2 + d3 * d3, sm) * (1.f / 1024.f);
    float rstd = rsqrtf(var + 1e-6f);
    float4 o = make_float4(d0 * rstd, d1 * rstd, d2 * rstd, d3 * rstd);
    if (shift_chunk >= 0) {
        const float4* shp = (const float4*)(mod + (size_t)b * 6 * Dv + shift_chunk * Dv);
        const float4* scp = (const float4*)(mod + (size_t)b * 6 * Dv + (shift_chunk + 1) * Dv);
        float4 sh = shp[threadIdx.x], sc = scp[threadIdx.x];
        o.x = o.x * (1.f + sc.x) + sh.x;
        o.y = o.y * (1.f + sc.y) + sh.y;
        o.z = o.z * (1.f + sc.z) + sh.z;
        o.w = o.w * (1.f + sc.w) + sh.w;
    }
    ((float4*)(out + (size_t)row * Dv))[threadIdx.x] = o;
}

// ---------------- double-buffered SGEMM with fused epilogue ----------------
// C = epi(A@W + bias); optionally C = res + gate*(...) (gated residual).
// A: MxK row-major, W: KxN row-major. N%128==0, K%8==0; M arbitrary.
// res != nullptr -> residual add; gate_chunk >= 0 -> multiply by mod gate
// (valid only when N == Dv and rows map (b*1024 + n) with b = m>>10).
#define GELU_F(v) (0.5f * (v) * (1.f + erff((v)*0.7071067811865475f)))

__global__ __launch_bounds__(256) void sgemm_kernel(
    const float* __restrict__ A, const float* __restrict__ W,
    const float* __restrict__ bias, float* __restrict__ C,
    int M, int N, int K, int epi,
    const float* __restrict__ res, const float* __restrict__ modp,
    int gate_chunk) {
    __shared__ float As[2][8][128];
    __shared__ float Bs[2][8][128];
    int tid = threadIdx.x;
    int bm = blockIdx.y * 128;
    int bn = blockIdx.x * 128;
    int a_row = tid >> 1;
    int a_k = (tid & 1) * 4;
    int b_k = tid >> 5;
    int b_n = (tid & 31) * 4;
    int tx = tid & 15, ty = tid >> 4;
    float acc[8][8];
    #pragma unroll
    for (int i = 0; i < 8; i++)
        #pragma unroll
        for (int j = 0; j < 8; j++) acc[i][j] = 0.f;

    const float* Aptr = A + (size_t)(bm + a_row) * K + a_k;
    const float* Wptr = W + (size_t)b_k * N + bn + b_n;
    bool a_valid = (bm + a_row) < M;
    int ntiles = K >> 3;

    // prologue: load tile 0 into buffer 0
    {
        float4 av = a_valid ? *(const float4*)Aptr : make_float4(0.f, 0.f, 0.f, 0.f);
        float4 wv = *(const float4*)Wptr;
        As[0][a_k + 0][a_row] = av.x;
        As[0][a_k + 1][a_row] = av.y;
        As[0][a_k + 2][a_row] = av.z;
        As[0][a_k + 3][a_row] = av.w;
        *(float4*)&Bs[0][b_k][b_n] = wv;
    }
    __syncthreads();

    int buf = 0;
    for (int t = 0; t < ntiles; t++) {
        float4 av_n = make_float4(0.f, 0.f, 0.f, 0.f), wv_n;
        bool have_next = (t + 1) < ntiles;
        if (have_next) {
            const float* Ap = Aptr + 8;
            const float* Wp = Wptr + (size_t)8 * N;
            if (a_valid) av_n = *(const float4*)Ap;
            wv_n = *(const float4*)Wp;
        }
        #pragma unroll
        for (int kk = 0; kk < 8; kk++) {
            float4 a0 = *(const float4*)&As[buf][kk][ty * 4];
            float4 a1 = *(const float4*)&As[buf][kk][64 + ty * 4];
            float4 b0 = *(const float4*)&Bs[buf][kk][tx * 4];
            float4 b1 = *(const float4*)&Bs[buf][kk][64 + tx * 4];
            float am[8] = {a0.x, a0.y, a0.z, a0.w, a1.x, a1.y, a1.z, a1.w};
            float bb[8] = {b0.x, b0.y, b0.z, b0.w, b1.x, b1.y, b1.z, b1.w};
            #pragma unroll
            for (int i = 0; i < 8; i++)
                #pragma unroll
                for (int j = 0; j < 8; j++) acc[i][j] += am[i] * bb[j];
        }
        if (have_next) {
            int nb = buf ^ 1;
            As[nb][a_k + 0][a_row] = av_n.x;
            As[nb][a_k + 1][a_row] = av_n.y;
            As[nb][a_k + 2][a_row] = av_n.z;
            As[nb][a_k + 3][a_row] = av_n.w;
            *(float4*)&Bs[nb][b_k][b_n] = wv_n;
            __syncthreads();
            buf = nb;
            Aptr += 8;
            Wptr += (size_t)8 * N;
        }
    }
    #pragma unroll
    for (int i = 0; i < 8; i++) {
        int m = bm + ((i < 4) ? (ty * 4 + i) : (64 + ty * 4 + i - 4));
        if (m >= M) continue;
        int b = m >> 10;  // only used when res/gate active (N==Dv, M==B*N)
        #pragma unroll
        for (int jj = 0; jj < 2; jj++) {
            int n0 = bn + ((jj == 0) ? (tx * 4) : (64 + tx * 4));
            float4 bv = *(const float4*)(bias + n0);
            float4 o;
            o.x = acc[i][jj * 4 + 0] + bv.x;
            o.y = acc[i][jj * 4 + 1] + bv.y;
            o.z = acc[i][jj * 4 + 2] + bv.z;
            o.w = acc[i][jj * 4 + 3] + bv.w;
            if (epi == EPI_GELU) {
                o.x = GELU_F(o.x); o.y = GELU_F(o.y);
                o.z = GELU_F(o.z); o.w = GELU_F(o.w);
            }
            if (res != nullptr) {
                float4 rv = *(const float4*)(res + (size_t)m * N + n0);
                if (gate_chunk >= 0) {
                    float4 g = *(const float4*)(modp + (size_t)b * 6 * Dv +
                                                gate_chunk * Dv + n0);
                    o.x = rv.x + g.x * o.x;
                    o.y = rv.y + g.y * o.y;
                    o.z = rv.z + g.z * o.z;
                    o.w = rv.w + g.w * o.w;
                } else {
                    o.x += rv.x; o.y += rv.y; o.z += rv.z; o.w += rv.w;
                }
            }
            *(float4*)(C + (size_t)m * N + n0) = o;
        }
    }
}

// -------------------------- self-attention ---------------------------------
// scores[b,h,n,m] = (q . k) * SCALE ; qkv layout (B,N,3,H,HD)
__global__ __launch_bounds__(256) void sa_scores_kernel(
    const float* __restrict__ qkv, float* __restrict__ scores) {
    __shared__ float Qs[64][68];  // [d][q]
    __shared__ float Ks[64][68];  // [d][key]
    int qt = blockIdx.x;          // 0..15
    int bh = blockIdx.y;          // 0..63
    int b = bh >> 4, h = bh & 15;
    int tid = threadIdx.x;
    int lrow = tid >> 2;
    int lc0 = (tid & 3) * 16;
    int tx = tid & 15, ty = tid >> 4;
    {
        size_t base = ((size_t)(b * Nv + qt * 64 + lrow) * 3) * Dv + h * HDv;
        #pragma unroll
        for (int j = 0; j < 4; j++) {
            float4 v = *(const float4*)(qkv + base + lc0 + j * 4);
            int d = lc0 + j * 4;
            Qs[d + 0][lrow] = v.x; Qs[d + 1][lrow] = v.y;
            Qs[d + 2][lrow] = v.z; Qs[d + 3][lrow] = v.w;
        }
    }
    float* srow = scores + ((size_t)bh * Nv + qt * 64) * Nv;
    for (int kt = 0; kt < 16; kt++) {
        __syncthreads();
        {
            size_t base = ((size_t)(b * Nv + kt * 64 + lrow) * 3 + 1) * Dv + h * HDv;
            #pragma unroll
            for (int j = 0; j < 4; j++) {
                float4 v = *(const float4*)(qkv + base + lc0 + j * 4);
                int d = lc0 + j * 4;
                Ks[d + 0][lrow] = v.x; Ks[d + 1][lrow] = v.y;
                Ks[d + 2][lrow] = v.z; Ks[d + 3][lrow] = v.w;
            }
        }
        __syncthreads();
        float acc[4][4] = {};
        #pragma unroll 8
        for (int d = 0; d < 64; d++) {
            float4 q4 = *(const float4*)&Qs[d][ty * 4];
            float4 k4 = *(const float4*)&Ks[d][tx * 4];
            float qa[4] = {q4.x, q4.y, q4.z, q4.w};
            float ka[4] = {k4.x, k4.y, k4.z, k4.w};
            #pragma unroll
            for (int i = 0; i < 4; i++)
                #pragma unroll
                for (int j = 0; j < 4; j++) acc[i][j] += qa[i] * ka[j];
        }
        #pragma unroll
        for (int i = 0; i < 4; i++) {
            float4 o = make_float4(acc[i][0] * ATT_SCALE, acc[i][1] * ATT_SCALE,
                                   acc[i][2] * ATT_SCALE, acc[i][3] * ATT_SCALE);
            *(float4*)(srow + (size_t)(ty * 4 + i) * Nv + kt * 64 + tx * 4) = o;
        }
    }
}

__global__ __launch_bounds__(256) void softmax_n_kernel(float* __restrict__ sc) {
    __shared__ float sm[8];
    size_t row = blockIdx.x;
    float4* p = (float4*)(sc + row * Nv) + threadIdx.x;
    float4 v = *p;
    float m = fmaxf(fmaxf(v.x, v.y), fmaxf(v.z, v.w));
    m = blockReduceMax(m, sm);
    float4 e = make_float4(__expf(v.x - m), __expf(v.y - m),
                           __expf(v.z - m), __expf(v.w - m));
    float s = blockReduceSum(e.x + e.y + e.z + e.w, sm);
    float inv = 1.f / s;
    e.x *= inv; e.y *= inv; e.z *= inv; e.w *= inv;
    *p = e;
}

// sa[b,n,h*HD+d] = sum_m attn[b,h,n,m] * v[b,m,h,d]
__global__ __launch_bounds__(256) void attn_v_kernel(
    const float* __restrict__ scores, const float* __restrict__ qkv,
    float* __restrict__ out) {
    __shared__ float At[64][68];  // [key][q]
    __shared__ float Vs[64][68];  // [key][d]
    int qt = blockIdx.x, bh = blockIdx.y;
    int b = bh >> 4, h = bh & 15;
    int tid = threadIdx.x;
    int lrow = tid >> 2;
    int lc0 = (tid & 3) * 16;
    int tx = tid & 15, ty = tid >> 4;
    float acc[4][4] = {};
    const float* srow = scores + ((size_t)bh * Nv + qt * 64) * Nv;
    for (int kt = 0; kt < 16; kt++) {
        #pragma unroll
        for (int j = 0; j < 4; j++) {
            float4 v = *(const float4*)(srow + (size_t)lrow * Nv + kt * 64 + lc0 + j * 4);
            int c = lc0 + j * 4;
            At[c + 0][lrow] = v.x; At[c + 1][lrow] = v.y;
            At[c + 2][lrow] = v.z; At[c + 3][lrow] = v.w;
        }
        {
            size_t base = ((size_t)(b * Nv + kt * 64 + lrow) * 3 + 2) * Dv + h * HDv;
            #pragma unroll
            for (int j = 0; j < 4; j++)
                *(float4*)&Vs[lrow][lc0 + j * 4] = *(const float4*)(qkv + base + lc0 + j * 4);
        }
        __syncthreads();
        #pragma unroll 8
        for (int kk = 0; kk < 64; kk++) {
            float4 a4 = *(const float4*)&At[kk][ty * 4];
            float4 v4 = *(const float4*)&Vs[kk][tx * 4];
            float aa[4] = {a4.x, a4.y, a4.z, a4.w};
            float vv[4] = {v4.x, v4.y, v4.z, v4.w};
            #pragma unroll
            for (int i = 0; i < 4; i++)
                #pragma unroll
                for (int j = 0; j < 4; j++) acc[i][j] += aa[i] * vv[j];
        }
        __syncthreads();
    }
    #pragma unroll
    for (int i = 0; i < 4; i++) {
        int q = qt * 64 + ty * 4 + i;
        *(float4*)(out + (size_t)(b * Nv + q) * Dv + h * HDv + tx * 4) =
            make_float4(acc[i][0], acc[i][1], acc[i][2], acc[i][3]);
    }
}

// -------------------------- cross-attention --------------------------------
// cscores[b,h,n,s] = (qc . kc)*SCALE (masked -> -inf). kvc layout (B,S,2,H,HD)
__global__ __launch_bounds__(256) void ca_scores_kernel(
    const float* __restrict__ qc, const float* __restrict__ kvc,
    const char* __restrict__ mask, float* __restrict__ cs) {
    __shared__ float Qs[64][68];  // [d][q]
    __shared__ float Kt[64][80];  // [d][s]
    int qt = blockIdx.x, bh = blockIdx.y;
    int b = bh >> 4, h = bh & 15;
    int tid = threadIdx.x;
    int lrow = tid >> 2;
    int lc0 = (tid & 3) * 16;
    {
        size_t base = (size_t)(b * Nv + qt * 64 + lrow) * Dv + h * HDv;
        #pragma unroll
        for (int j = 0; j < 4; j++) {
            float4 v = *(const float4*)(qc + base + lc0 + j * 4);
            int d = lc0 + j * 4;
            Qs[d + 0][lrow] = v.x; Qs[d + 1][lrow] = v.y;
            Qs[d + 2][lrow] = v.z; Qs[d + 3][lrow] = v.w;
        }
    }
    for (int idx = tid; idx < Sv * 16; idx += 256) {
        int s = idx >> 4;
        int d0 = (idx & 15) * 4;
        float4 v = *(const float4*)(kvc + ((size_t)(b * Sv + s) * 2) * Dv + h * HDv + d0);
        Kt[d0 + 0][s] = v.x; Kt[d0 + 1][s] = v.y;
        Kt[d0 + 2][s] = v.z; Kt[d0 + 3][s] = v.w;
    }
    __syncthreads();
    int q = tid >> 2;
    int sl = tid & 3;
    float acc[20];
    #pragma unroll
    for (int j = 0; j < 20; j++) acc[j] = 0.f;
    #pragma unroll 4
    for (int d = 0; d < 64; d++) {
        float qv = Qs[d][q];
        #pragma unroll
        for (int j = 0; j < 20; j++) {
            int s = sl + j * 4;
            if (s < Sv) acc[j] += qv * Kt[d][s];
        }
    }
    size_t rbase = ((size_t)bh * Nv + qt * 64 + q) * Sv;
    #pragma unroll
    for (int j = 0; j < 20; j++) {
        int s = sl + j * 4;
        if (s < Sv) {
            float v = mask[b * Sv + s] ? -INFINITY : acc[j] * ATT_SCALE;
            cs[rbase + s] = v;
        }
    }
}

__global__ void softmax_s_kernel(float* __restrict__ cs) {
    __shared__ float sm[8];
    size_t row = blockIdx.x;
    float v = (threadIdx.x < Sv) ? cs[row * Sv + threadIdx.x] : -INFINITY;
    float m = blockReduceMax(v, sm);
    float e = (threadIdx.x < Sv) ? __expf(v - m) : 0.f;
    float s = blockReduceSum(e, sm);
    if (threadIdx.x < Sv) cs[row * Sv + threadIdx.x] = e / s;
}

// ca[b,n,h*HD+d] = sum_s attn_c[b,h,n,s] * vc[b,s,h,d]
__global__ __launch_bounds__(256) void ca_av_kernel(
    const float* __restrict__ cs, const float* __restrict__ kvc,
    float* __restrict__ out) {
    __shared__ float At[Sv][68];  // [s][q]
    __shared__ float Vs[Sv][68];  // [s][d]
    int qt = blockIdx.x, bh = blockIdx.y;
    int b = bh >> 4, h = bh & 15;
    int tid = threadIdx.x;
    for (int idx = tid; idx < 64 * Sv; idx += 256) {
        int q = idx / Sv, s = idx % Sv;
        At[s][q] = cs[((size_t)bh * Nv + qt * 64 + q) * Sv + s];
    }
    for (int idx = tid; idx < Sv * 16; idx += 256) {
        int s = idx >> 4, d0 = (idx & 15) * 4;
        *(float4*)&Vs[s][d0] =
            *(const float4*)(kvc + ((size_t)(b * Sv + s) * 2 + 1) * Dv + h * HDv + d0);
    }
    __syncthreads();
    int tx = tid & 15, ty = tid >> 4;
    float acc[4][4] = {};
    #pragma unroll 7
    for (int s = 0; s < Sv; s++) {
        float4 a4 = *(const float4*)&At[s][ty * 4];
        float4 v4 = *(const float4*)&Vs[s][tx * 4];
        float aa[4] = {a4.x, a4.y, a4.z, a4.w};
        float vv[4] = {v4.x, v4.y, v4.z, v4.w};
        #pragma unroll
        for (int i = 0; i < 4; i++)
            #pragma unroll
            for (int j = 0; j < 4; j++) acc[i][j] += aa[i] * vv[j];
    }
    #pragma unroll
    for (int i = 0; i < 4; i++) {
        int q = qt * 64 + ty * 4 + i;
        *(float4*)(out + (size_t)(b * Nv + q) * Dv + h * HDv + tx * 4) =
            make_float4(acc[i][0], acc[i][1], acc[i][2], acc[i][3]);
    }
}

// -------------------------- launch -----------------------------------------
extern "C" void kernel_launch(void* const* d_in, const int* in_sizes, int n_in,
                              void* d_out, int out_size) {
    const float* x      = (const float*)d_in[0];
    const float* t_emb  = (const float*)d_in[1];
    const float* ctx    = (const float*)d_in[2];
    const char*  cmask  = (const char*)d_in[3];
    const float* ada_w  = (const float*)d_in[4];
    const float* ada_b  = (const float*)d_in[5];
    const float* qkv_w  = (const float*)d_in[6];
    const float* qkv_b  = (const float*)d_in[7];
    const float* sa_w   = (const float*)d_in[8];
    const float* sa_b   = (const float*)d_in[9];
    const float* q_w    = (const float*)d_in[10];
    const float* q_b    = (const float*)d_in[11];
    const float* kv_w   = (const float*)d_in[12];
    const float* kv_b   = (const float*)d_in[13];
    const float* ca_w   = (const float*)d_in[14];
    const float* ca_b   = (const float*)d_in[15];
    const float* fc1_w  = (const float*)d_in[16];
    const float* fc1_b  = (const float*)d_in[17];
    const float* fc2_w  = (const float*)d_in[18];
    const float* fc2_b  = (const float*)d_in[19];
    float* out = (float*)d_out;

    float *ts, *mod, *xm1, *qkv, *sc, *sa, *x1, *xn2, *qc, *kvc, *cs, *ca,
          *x2, *xm3, *hb;
    cudaGetSymbolAddress((void**)&ts,  g_ts);
    cudaGetSymbolAddress((void**)&mod, g_mod);
    cudaGetSymbolAddress((void**)&xm1, g_xm1);
    cudaGetSymbolAddress((void**)&qkv, g_qkv);
    cudaGetSymbolAddress((void**)&sc,  g_scores);
    cudaGetSymbolAddress((void**)&sa,  g_sa);
    cudaGetSymbolAddress((void**)&x1,  g_x1);
    cudaGetSymbolAddress((void**)&xn2, g_xn2);
    cudaGetSymbolAddress((void**)&qc,  g_qc);
    cudaGetSymbolAddress((void**)&kvc, g_kvc);
    cudaGetSymbolAddress((void**)&cs,  g_cs);
    cudaGetSymbolAddress((void**)&ca,  g_ca);
    cudaGetSymbolAddress((void**)&x2,  g_x2);
    cudaGetSymbolAddress((void**)&xm3, g_xm3);
    cudaGetSymbolAddress((void**)&hb,  g_h);

    // 1. modulation
    silu_kernel<<<16, 256>>>(t_emb, ts);
    mod_gemm_kernel<<<24, 256>>>(ts, ada_w, ada_b, mod);

    // 2. self-attention branch
    ln_kernel<<<Bv * Nv, 256>>>(x, mod, 0, xm1);                      // shift_sa/scale_sa
    sgemm_kernel<<<dim3(24, 32), 256>>>(xm1, qkv_w, qkv_b, qkv,
                                        Bv * Nv, 3 * Dv, Dv, EPI_NONE,
                                        nullptr, nullptr, -1);
    sa_scores_kernel<<<dim3(16, 64), 256>>>(qkv, sc);
    softmax_n_kernel<<<Bv * Hv * Nv, 256>>>(sc);
    attn_v_kernel<<<dim3(16, 64), 256>>>(sc, qkv, sa);
    // x1 = x + gate_sa * (sa @ sa_w + sa_b)    [fused epilogue]
    sgemm_kernel<<<dim3(8, 32), 256>>>(sa, sa_w, sa_b, x1,
                                       Bv * Nv, Dv, Dv, EPI_NONE,
                                       x, mod, 2);

    // 3. cross-attention branch
    ln_kernel<<<Bv * Nv, 256>>>(x1, mod, -1, xn2);
    sgemm_kernel<<<dim3(8, 32), 256>>>(xn2, q_w, q_b, qc,
                                       Bv * Nv, Dv, Dv, EPI_NONE,
                                       nullptr, nullptr, -1);
    sgemm_kernel<<<dim3(16, 3), 256>>>(ctx, kv_w, kv_b, kvc,
                                       Bv * Sv, 2 * Dv, Dv, EPI_NONE,
                                       nullptr, nullptr, -1);
    ca_scores_kernel<<<dim3(16, 64), 256>>>(qc, kvc, cmask, cs);
    softmax_s_kernel<<<Bv * Hv * Nv, 128>>>(cs);
    ca_av_kernel<<<dim3(16, 64), 256>>>(cs, kvc, ca);
    // x2 = x1 + (ca @ ca_w + ca_b)             [fused epilogue, no gate]
    sgemm_kernel<<<dim3(8, 32), 256>>>(ca, ca_w, ca_b, x2,
                                       Bv * Nv, Dv, Dv, EPI_NONE,
                                       x1, nullptr, -1);

    // 4. MLP branch
    ln_kernel<<<Bv * Nv, 256>>>(x2, mod, 3, xm3);                     // shift_ff/scale_ff
    sgemm_kernel<<<dim3(32, 32), 256>>>(xm3, fc1_w, fc1_b, hb,
                                        Bv * Nv, DFv, Dv, EPI_GELU,
                                        nullptr, nullptr, -1);
    // out = x2 + gate_ff * (h @ fc2_w + fc2_b) [fused epilogue]
    sgemm_kernel<<<dim3(8, 32), 256>>>(hb, fc2_w, fc2_b, out,
                                       Bv * Nv, Dv, DFv, EPI_NONE,
                                       x2, mod, 5);
}

// round 12
// speedup vs baseline: 1.7543x; 1.7543x over previous
#include <cuda_runtime.h>
#include <cuda_bf16.h>
#include <math.h>
#include <stdint.h>

// ---------------------------------------------------------------------------
// VS_DiT_Block: B=4, N=1024, D=1024, H=16, HD=64, S=77, DF=4096
// GEMMs on mma.sync bf16 (HMMA, 3-term hi/lo split ~ fp32 accuracy), fused
// epilogues (bias/GELU/gated-residual/bf16-split), cp.async 3-stage pipeline.
// LN and attention outputs write bf16 hi/lo directly (split fused).
// Self-attn softmax fused into attn_v; cross-attn softmax fused into ca_av.
// Attention/LN/softmax math fp32. (tcgen05 unavailable on base sm_103 target.)
// ---------------------------------------------------------------------------

#define Bv 4
#define Nv 1024
#define Dv 1024
#define Hv 16
#define HDv 64
#define Sv 77
#define DFv 4096
#define ATT_SCALE 0.125f

#define EPI_NONE 0
#define EPI_GELU 1
#define EPI_GELU_SPLIT 2

// -------------------------- device scratch (no malloc allowed) -------------
__device__ float g_ts[Bv * Dv];
__device__ float g_mod[Bv * 6 * Dv];
__device__ float g_qkv[Bv * Nv * 3 * Dv];
__device__ float g_scores[(size_t)Bv * Hv * Nv * Nv];
__device__ float g_x1[Bv * Nv * Dv];
__device__ float g_qc[Bv * Nv * Dv];
__device__ float g_kvc[Bv * Sv * 2 * Dv];
__device__ float g_cs[(size_t)Bv * Hv * Nv * Sv];
__device__ float g_x2[Bv * Nv * Dv];
__device__ float g_h[Bv * Nv * DFv];   // reused as 2 bf16 planes (fc1 hi/lo)

#define WTOT 16777216
__device__ __nv_bfloat16 g_whi[WTOT];
__device__ __nv_bfloat16 g_wlo[WTOT];
__device__ __nv_bfloat16 g_ahi[WTOT];
__device__ __nv_bfloat16 g_alo[WTOT];

#define OFF_QKV 0
#define OFF_SAP 3145728
#define OFF_QW  4194304
#define OFF_KV  5242880
#define OFF_CAP 7340032
#define OFF_FC1 8388608
#define OFF_FC2 12582912

// -------------------------- reduction helpers ------------------------------
__device__ __forceinline__ float warpReduceSum(float v) {
    #pragma unroll
    for (int o = 16; o > 0; o >>= 1) v += __shfl_xor_sync(0xffffffffu, v, o);
    return v;
}
__device__ __forceinline__ float blockReduceSum(float v, float* sm) {
    int w = threadIdx.x >> 5, l = threadIdx.x & 31;
    v = warpReduceSum(v);
    if (l == 0) sm[w] = v;
    __syncthreads();
    int nw = blockDim.x >> 5;
    float r = 0.f;
    for (int i = 0; i < nw; i++) r += sm[i];
    __syncthreads();
    return r;
}

// -------------------------- bf16 split helpers -----------------------------
__device__ __forceinline__ void bf_split(float f, __nv_bfloat16& h, __nv_bfloat16& l) {
    h = __float2bfloat16(f);
    l = __float2bfloat16(f - __bfloat162float(h));
}

// -------------------------- pointwise kernels ------------------------------
__global__ void silu_kernel(const float* __restrict__ t, float* __restrict__ out) {
    int i = blockIdx.x * 256 + threadIdx.x;
    if (i < Bv * Dv) {
        float v = t[i];
        out[i] = v / (1.f + __expf(-v));
    }
}

__global__ __launch_bounds__(256) void mod_gemm_kernel(
    const float* __restrict__ ts, const float* __restrict__ ada_w,
    const float* __restrict__ ada_b, float* __restrict__ mod) {
    __shared__ float s_ts[Bv][Dv];
    int tid = threadIdx.x;
    for (int i = tid; i < Bv * Dv; i += 256) s_ts[i >> 10][i & 1023] = ts[i];
    __syncthreads();
    int col = blockIdx.x * 256 + tid;
    float a0 = 0.f, a1 = 0.f, a2 = 0.f, a3 = 0.f;
    #pragma unroll 4
    for (int k = 0; k < Dv; k++) {
        float w = ada_w[(size_t)k * (6 * Dv) + col];
        a0 += s_ts[0][k] * w;
        a1 += s_ts[1][k] * w;
        a2 += s_ts[2][k] * w;
        a3 += s_ts[3][k] * w;
    }
    float bb = ada_b[col];
    mod[0 * 6 * Dv + col] = a0 + bb;
    mod[1 * 6 * Dv + col] = a1 + bb;
    mod[2 * 6 * Dv + col] = a2 + bb;
    mod[3 * 6 * Dv + col] = a3 + bb;
}

// LayerNorm (+ optional shift/scale modulation) -> bf16 hi/lo split output.
__global__ __launch_bounds__(256) void ln_split_kernel(
    const float* __restrict__ x, const float* __restrict__ mod,
    int shift_chunk, __nv_bfloat16* __restrict__ hi,
    __nv_bfloat16* __restrict__ lo) {
    __shared__ float sm[8];
    int row = blockIdx.x;
    int b = row >> 10;
    const float4* xr = (const float4*)(x + (size_t)row * Dv);
    float4 v = xr[threadIdx.x];
    float mean = blockReduceSum(v.x + v.y + v.z + v.w, sm) * (1.f / 1024.f);
    float d0 = v.x - mean, d1 = v.y - mean, d2 = v.z - mean, d3 = v.w - mean;
    float var = blockReduceSum(d0 * d0 + d1 * d1 + d2 * d2 + d3 * d3, sm) * (1.f / 1024.f);
    float rstd = rsqrtf(var + 1e-6f);
    float4 o = make_float4(d0 * rstd, d1 * rstd, d2 * rstd, d3 * rstd);
    if (shift_chunk >= 0) {
        const float4* shp = (const float4*)(mod + (size_t)b * 6 * Dv + shift_chunk * Dv);
        const float4* scp = (const float4*)(mod + (size_t)b * 6 * Dv + (shift_chunk + 1) * Dv);
        float4 sh = shp[threadIdx.x], sc = scp[threadIdx.x];
        o.x = o.x * (1.f + sc.x) + sh.x;
        o.y = o.y * (1.f + sc.y) + sh.y;
        o.z = o.z * (1.f + sc.z) + sh.z;
        o.w = o.w * (1.f + sc.w) + sh.w;
    }
    __nv_bfloat16 h0, h1, h2, h3, l0, l1, l2, l3;
    bf_split(o.x, h0, l0); bf_split(o.y, h1, l1);
    bf_split(o.z, h2, l2); bf_split(o.w, h3, l3);
    __nv_bfloat162* hp = (__nv_bfloat162*)(hi + (size_t)row * Dv);
    __nv_bfloat162* lp = (__nv_bfloat162*)(lo + (size_t)row * Dv);
    hp[threadIdx.x * 2 + 0] = __nv_bfloat162(h0, h1);
    hp[threadIdx.x * 2 + 1] = __nv_bfloat162(h2, h3);
    lp[threadIdx.x * 2 + 0] = __nv_bfloat162(l0, l1);
    lp[threadIdx.x * 2 + 1] = __nv_bfloat162(l2, l3);
}

// plain elementwise split (used for context only)
__global__ void split_kernel(const float* __restrict__ A,
                             __nv_bfloat16* __restrict__ hi,
                             __nv_bfloat16* __restrict__ lo, int n4) {
    int i = blockIdx.x * 256 + threadIdx.x;
    if (i >= n4) return;
    float4 f = ((const float4*)A)[i];
    __nv_bfloat16 h0, h1, h2, h3, l0, l1, l2, l3;
    bf_split(f.x, h0, l0); bf_split(f.y, h1, l1);
    bf_split(f.z, h2, l2); bf_split(f.w, h3, l3);
    __nv_bfloat162* hp = (__nv_bfloat162*)hi;
    __nv_bfloat162* lp = (__nv_bfloat162*)lo;
    hp[i * 2 + 0] = __nv_bfloat162(h0, h1);
    hp[i * 2 + 1] = __nv_bfloat162(h2, h3);
    lp[i * 2 + 0] = __nv_bfloat162(l0, l1);
    lp[i * 2 + 1] = __nv_bfloat162(l2, l3);
}

// W [K][N] fp32 -> whi/wlo [N][K] bf16
__global__ __launch_bounds__(256) void transp_split_kernel(
    const float* __restrict__ W, __nv_bfloat16* __restrict__ whi,
    __nv_bfloat16* __restrict__ wlo, int K, int N) {
    __shared__ float s[32][33];
    int tx = threadIdx.x, ty = threadIdx.y;
    int n0 = blockIdx.x * 32, k0 = blockIdx.y * 32;
    #pragma unroll
    for (int j = 0; j < 32; j += 8)
        s[ty + j][tx] = W[(size_t)(k0 + ty + j) * N + n0 + tx];
    __syncthreads();
    #pragma unroll
    for (int j = 0; j < 32; j += 8) {
        float f = s[tx][ty + j];
        __nv_bfloat16 h, l;
        bf_split(f, h, l);
        size_t o = (size_t)(n0 + ty + j) * K + k0 + tx;
        whi[o] = h;
        wlo[o] = l;
    }
}

// -------------------------- HMMA bf16 GEMM ---------------------------------
#define KC 32
#define ST 3
#define RS 40
#define TILE_BY (128 * RS * 2)      // 10240 B per tile
#define STG_BY (4 * TILE_BY)        // Ah, Al, Bh, Bl per stage
#define GMM_SMEM (ST * STG_BY)      // 122880 B

__device__ __forceinline__ uint32_t smem_u32(const void* p) {
    uint32_t a;
    asm("{ .reg .u64 t; cvta.to.shared.u64 t, %1; cvt.u32.u64 %0, t; }"
        : "=r"(a) : "l"(p));
    return a;
}

__device__ __forceinline__ void cp16(uint32_t dst, const void* src, bool v) {
    int sz = v ? 16 : 0;
    asm volatile("cp.async.ca.shared.global [%0], [%1], 16, %2;"
                 :: "r"(dst), "l"(src), "r"(sz));
}

#define LDSM4(r, addr) \
    asm volatile("ldmatrix.sync.aligned.m8n8.x4.shared.b16 {%0,%1,%2,%3}, [%4];" \
        : "=r"((r)[0]), "=r"((r)[1]), "=r"((r)[2]), "=r"((r)[3]) : "r"(addr))

#define MMA16816(d, a, b0, b1) \
    asm volatile("mma.sync.aligned.m16n8k16.row.col.f32.bf16.bf16.f32 " \
        "{%0,%1,%2,%3}, {%4,%5,%6,%7}, {%8,%9}, {%0,%1,%2,%3};" \
        : "+f"((d)[0]), "+f"((d)[1]), "+f"((d)[2]), "+f"((d)[3]) \
        : "r"((a)[0]), "r"((a)[1]), "r"((a)[2]), "r"((a)[3]), "r"(b0), "r"(b1))

__device__ __forceinline__ void ld_stage(
    uint32_t sbase,
    const __nv_bfloat16* __restrict__ Ah, const __nv_bfloat16* __restrict__ Al,
    const __nv_bfloat16* __restrict__ Bh, const __nv_bfloat16* __restrict__ Bl,
    int bm, int bn, int M, int K, int k0, int tid) {
    #pragma unroll
    for (int it = 0; it < 8; it++) {
        int idx = it * 256 + tid;
        int tile = idx >> 9;
        int r = (idx >> 2) & 127;
        int seg = idx & 3;
        uint32_t dst = sbase + tile * TILE_BY + (uint32_t)(r * RS + seg * 8) * 2;
        if (tile < 2) {
            bool v = (bm + r) < M;
            int rr = v ? (bm + r) : 0;
            const __nv_bfloat16* base = (tile == 0) ? Ah : Al;
            cp16(dst, base + (size_t)rr * K + k0 + seg * 8, v);
        } else {
            const __nv_bfloat16* base = (tile == 2) ? Bh : Bl;
            cp16(dst, base + (size_t)(bn + r) * K + k0 + seg * 8, true);
        }
    }
}

#define GELU_F(v) (0.5f * (v) * (1.f + erff((v)*0.7071067811865475f)))

__global__ __launch_bounds__(256) void gemm_mma(
    const __nv_bfloat16* __restrict__ Ahi, const __nv_bfloat16* __restrict__ Alo,
    const __nv_bfloat16* __restrict__ Bhi, const __nv_bfloat16* __restrict__ Blo,
    const float* __restrict__ bias, float* __restrict__ C,
    int M, int N, int K, int epi,
    const float* __restrict__ res, const float* __restrict__ modp,
    int gate_chunk,
    __nv_bfloat16* __restrict__ Chi, __nv_bfloat16* __restrict__ Clo) {
    extern __shared__ char smem[];
    uint32_t sb = smem_u32(smem);
    int tid = threadIdx.x, lane = tid & 31, wid = tid >> 5;
    int wm = wid & 3, wn = wid >> 2;
    int bm = blockIdx.y * 128, bn = blockIdx.x * 128;
    int nch = K >> 5;

    float acc[2][8][4];
    #pragma unroll
    for (int i = 0; i < 2; i++)
        #pragma unroll
        for (int j = 0; j < 8; j++)
            #pragma unroll
            for (int q = 0; q < 4; q++) acc[i][j][q] = 0.f;

    #pragma unroll
    for (int s = 0; s < ST - 1; s++) {
        ld_stage(sb + s * STG_BY, Ahi, Alo, Bhi, Blo, bm, bn, M, K, s * KC, tid);
        asm volatile("cp.async.commit_group;");
    }

    uint32_t a_row = wm * 32 + (lane & 15);
    uint32_t a_k = (lane >> 4) * 8;
    uint32_t b_row = wn * 64 + (lane >> 4) * 8 + (lane & 7);
    uint32_t b_k = ((lane >> 3) & 1) * 8;

    for (int c = 0; c < nch; c++) {
        asm volatile("cp.async.wait_group %0;" :: "n"(ST - 2));
        __syncthreads();
        if (c + ST - 1 < nch)
            ld_stage(sb + ((c + ST - 1) % ST) * STG_BY, Ahi, Alo, Bhi, Blo,
                     bm, bn, M, K, (c + ST - 1) * KC, tid);
        asm volatile("cp.async.commit_group;");

        uint32_t st = sb + (c % ST) * STG_BY;
        #pragma unroll
        for (int kk = 0; kk < KC; kk += 16) {
            uint32_t ah[2][4], al[2][4];
            #pragma unroll
            for (int mg = 0; mg < 2; mg++) {
                uint32_t aoff = ((a_row + mg * 16) * RS + a_k + kk) * 2;
                LDSM4(ah[mg], st + 0 * TILE_BY + aoff);
                LDSM4(al[mg], st + 1 * TILE_BY + aoff);
            }
            #pragma unroll
            for (int ng2 = 0; ng2 < 4; ng2++) {
                uint32_t boff = ((b_row + ng2 * 16) * RS + b_k + kk) * 2;
                uint32_t bh[4], bl[4];
                LDSM4(bh, st + 2 * TILE_BY + boff);
                LDSM4(bl, st + 3 * TILE_BY + boff);
                #pragma unroll
                for (int mg = 0; mg < 2; mg++) {
                    MMA16816(acc[mg][2 * ng2 + 0], ah[mg], bh[0], bh[1]);
                    MMA16816(acc[mg][2 * ng2 + 0], ah[mg], bl[0], bl[1]);
                    MMA16816(acc[mg][2 * ng2 + 0], al[mg], bh[0], bh[1]);
                    MMA16816(acc[mg][2 * ng2 + 1], ah[mg], bh[2], bh[3]);
                    MMA16816(acc[mg][2 * ng2 + 1], ah[mg], bl[2], bl[3]);
                    MMA16816(acc[mg][2 * ng2 + 1], al[mg], bh[2], bh[3]);
                }
            }
        }
    }

    // epilogue
    #pragma unroll
    for (int mg = 0; mg < 2; mg++) {
        #pragma unroll
        for (int pr = 0; pr < 2; pr++) {
            int m = bm + wm * 32 + mg * 16 + pr * 8 + (lane >> 2);
            if (m >= M) continue;
            int b = m >> 10;
            #pragma unroll
            for (int ng = 0; ng < 8; ng++) {
                int n = bn + wn * 64 + ng * 8 + (lane & 3) * 2;
                float2 bv = *(const float2*)(bias + n);
                float o0 = acc[mg][ng][pr * 2 + 0] + bv.x;
                float o1 = acc[mg][ng][pr * 2 + 1] + bv.y;
                if (epi == EPI_GELU_SPLIT) {
                    o0 = GELU_F(o0); o1 = GELU_F(o1);
                    __nv_bfloat16 h0, l0, h1, l1;
                    bf_split(o0, h0, l0);
                    bf_split(o1, h1, l1);
                    *(__nv_bfloat162*)(Chi + (size_t)m * N + n) = __nv_bfloat162(h0, h1);
                    *(__nv_bfloat162*)(Clo + (size_t)m * N + n) = __nv_bfloat162(l0, l1);
                    continue;
                }
                if (epi == EPI_GELU) { o0 = GELU_F(o0); o1 = GELU_F(o1); }
                if (res != nullptr) {
                    float2 rv = *(const float2*)(res + (size_t)m * N + n);
                    if (gate_chunk >= 0) {
                        float2 g = *(const float2*)(modp + (size_t)b * 6 * Dv +
                                                    gate_chunk * Dv + n);
                        o0 = rv.x + g.x * o0;
                        o1 = rv.y + g.y * o1;
                    } else {
                        o0 += rv.x; o1 += rv.y;
                    }
                }
                *(float2*)(C + (size_t)m * N + n) = make_float2(o0, o1);
            }
        }
    }
}

// -------------------------- self-attention (fp32) --------------------------
__global__ __launch_bounds__(256) void sa_scores_kernel(
    const float* __restrict__ qkv, float* __restrict__ scores) {
    __shared__ float Qs[64][68];
    __shared__ float Ks[64][68];
    int qt = blockIdx.x;
    int bh = blockIdx.y;
    int b = bh >> 4, h = bh & 15;
    int tid = threadIdx.x;
    int lrow = tid >> 2;
    int lc0 = (tid & 3) * 16;
    int tx = tid & 15, ty = tid >> 4;
    {
        size_t base = ((size_t)(b * Nv + qt * 64 + lrow) * 3) * Dv + h * HDv;
        #pragma unroll
        for (int j = 0; j < 4; j++) {
            float4 v = *(const float4*)(qkv + base + lc0 + j * 4);
            int d = lc0 + j * 4;
            Qs[d + 0][lrow] = v.x; Qs[d + 1][lrow] = v.y;
            Qs[d + 2][lrow] = v.z; Qs[d + 3][lrow] = v.w;
        }
    }
    float* srow = scores + ((size_t)bh * Nv + qt * 64) * Nv;
    for (int kt = 0; kt < 16; kt++) {
        __syncthreads();
        {
            size_t base = ((size_t)(b * Nv + kt * 64 + lrow) * 3 + 1) * Dv + h * HDv;
            #pragma unroll
            for (int j = 0; j < 4; j++) {
                float4 v = *(const float4*)(qkv + base + lc0 + j * 4);
                int d = lc0 + j * 4;
                Ks[d + 0][lrow] = v.x; Ks[d + 1][lrow] = v.y;
                Ks[d + 2][lrow] = v.z; Ks[d + 3][lrow] = v.w;
            }
        }
        __syncthreads();
        float acc[4][4] = {};
        #pragma unroll 8
        for (int d = 0; d < 64; d++) {
            float4 q4 = *(const float4*)&Qs[d][ty * 4];
            float4 k4 = *(const float4*)&Ks[d][tx * 4];
            float qa[4] = {q4.x, q4.y, q4.z, q4.w};
            float ka[4] = {k4.x, k4.y, k4.z, k4.w};
            #pragma unroll
            for (int i = 0; i < 4; i++)
                #pragma unroll
                for (int j = 0; j < 4; j++) acc[i][j] += qa[i] * ka[j];
        }
        #pragma unroll
        for (int i = 0; i < 4; i++) {
            float4 o = make_float4(acc[i][0] * ATT_SCALE, acc[i][1] * ATT_SCALE,
                                   acc[i][2] * ATT_SCALE, acc[i][3] * ATT_SCALE);
            *(float4*)(srow + (size_t)(ty * 4 + i) * Nv + kt * 64 + tx * 4) = o;
        }
    }
}

// sa = softmax(scores) @ V -> bf16 hi/lo split output. Softmax fused:
// phase 0 computes per-row max and sum(exp) (4 threads/row), main loop
// applies exp((v-max))/sum while staging score tiles.
__global__ __launch_bounds__(256) void attn_v_kernel(
    const float* __restrict__ scores, const float* __restrict__ qkv,
    __nv_bfloat16* __restrict__ hi, __nv_bfloat16* __restrict__ lo) {
    __shared__ float At[64][68];
    __shared__ float Vs[64][68];
    __shared__ float pbuf[64][4];
    __shared__ float rmax[64];
    __shared__ float rsum[64];
    int qt = blockIdx.x, bh = blockIdx.y;
    int b = bh >> 4, h = bh & 15;
    int tid = threadIdx.x;
    int lrow = tid >> 2;
    int lc0 = (tid & 3) * 16;
    int tx = tid & 15, ty = tid >> 4;
    const float* srow = scores + ((size_t)bh * Nv + qt * 64) * Nv;

    // phase 0: row max then row sum(exp) over 1024 keys; 4 threads per row
    {
        int part = tid & 3;
        const float4* sp = (const float4*)(srow + (size_t)lrow * Nv + part * 256);
        float m = -INFINITY;
        #pragma unroll 8
        for (int i = 0; i < 64; i++) {
            float4 v = sp[i];
            m = fmaxf(m, fmaxf(fmaxf(v.x, v.y), fmaxf(v.z, v.w)));
        }
        pbuf[lrow][part] = m;
        __syncthreads();
        float rm = fmaxf(fmaxf(pbuf[lrow][0], pbuf[lrow][1]),
                         fmaxf(pbuf[lrow][2], pbuf[lrow][3]));
        __syncthreads();
        float s = 0.f;
        #pragma unroll 8
        for (int i = 0; i < 64; i++) {
            float4 v = sp[i];
            s += __expf(v.x - rm) + __expf(v.y - rm) +
                 __expf(v.z - rm) + __expf(v.w - rm);
        }
        pbuf[lrow][part] = s;
        __syncthreads();
        if (part == 0) {
            rmax[lrow] = rm;
            rsum[lrow] = pbuf[lrow][0] + pbuf[lrow][1] +
                         pbuf[lrow][2] + pbuf[lrow][3];
        }
        __syncthreads();
    }
    float rmx = rmax[lrow];
    float rinv = 1.f / rsum[lrow];

    float acc[4][4] = {};
    for (int kt = 0; kt < 16; kt++) {
        #pragma unroll
        for (int j = 0; j < 4; j++) {
            float4 v = *(const float4*)(srow + (size_t)lrow * Nv + kt * 64 + lc0 + j * 4);
            int c = lc0 + j * 4;
            At[c + 0][lrow] = __expf(v.x - rmx) * rinv;
            At[c + 1][lrow] = __expf(v.y - rmx) * rinv;
            At[c + 2][lrow] = __expf(v.z - rmx) * rinv;
            At[c + 3][lrow] = __expf(v.w - rmx) * rinv;
        }
        {
            size_t base = ((size_t)(b * Nv + kt * 64 + lrow) * 3 + 2) * Dv + h * HDv;
            #pragma unroll
            for (int j = 0; j < 4; j++)
                *(float4*)&Vs[lrow][lc0 + j * 4] = *(const float4*)(qkv + base + lc0 + j * 4);
        }
        __syncthreads();
        #pragma unroll 8
        for (int kk = 0; kk < 64; kk++) {
            float4 a4 = *(const float4*)&At[kk][ty * 4];
            float4 v4 = *(const float4*)&Vs[kk][tx * 4];
            float aa[4] = {a4.x, a4.y, a4.z, a4.w};
            float vv[4] = {v4.x, v4.y, v4.z, v4.w};
            #pragma unroll
            for (int i = 0; i < 4; i++)
                #pragma unroll
                for (int j = 0; j < 4; j++) acc[i][j] += aa[i] * vv[j];
        }
        __syncthreads();
    }
    #pragma unroll
    for (int i = 0; i < 4; i++) {
        int q = qt * 64 + ty * 4 + i;
        size_t off = (size_t)(b * Nv + q) * Dv + h * HDv + tx * 4;
        __nv_bfloat16 h0, h1, h2, h3, l0, l1, l2, l3;
        bf_split(acc[i][0], h0, l0); bf_split(acc[i][1], h1, l1);
        bf_split(acc[i][2], h2, l2); bf_split(acc[i][3], h3, l3);
        *(__nv_bfloat162*)(hi + off)     = __nv_bfloat162(h0, h1);
        *(__nv_bfloat162*)(hi + off + 2) = __nv_bfloat162(h2, h3);
        *(__nv_bfloat162*)(lo + off)     = __nv_bfloat162(l0, l1);
        *(__nv_bfloat162*)(lo + off + 2) = __nv_bfloat162(l2, l3);
    }
}

// -------------------------- cross-attention (fp32) -------------------------
// writes raw masked scores (softmax fused into ca_av)
__global__ __launch_bounds__(256) void ca_scores_kernel(
    const float* __restrict__ qc, const float* __restrict__ kvc,
    const char* __restrict__ mask, float* __restrict__ cs) {
    __shared__ float Qs[64][68];
    __shared__ float Kt[64][80];
    int qt = blockIdx.x, bh = blockIdx.y;
    int b = bh >> 4, h = bh & 15;
    int tid = threadIdx.x;
    int lrow = tid >> 2;
    int lc0 = (tid & 3) * 16;
    {
        size_t base = (size_t)(b * Nv + qt * 64 + lrow) * Dv + h * HDv;
        #pragma unroll
        for (int j = 0; j < 4; j++) {
            float4 v = *(const float4*)(qc + base + lc0 + j * 4);
            int d = lc0 + j * 4;
            Qs[d + 0][lrow] = v.x; Qs[d + 1][lrow] = v.y;
            Qs[d + 2][lrow] = v.z; Qs[d + 3][lrow] = v.w;
        }
    }
    for (int idx = tid; idx < Sv * 16; idx += 256) {
        int s = idx >> 4;
        int d0 = (idx & 15) * 4;
        float4 v = *(const float4*)(kvc + ((size_t)(b * Sv + s) * 2) * Dv + h * HDv + d0);
        Kt[d0 + 0][s] = v.x; Kt[d0 + 1][s] = v.y;
        Kt[d0 + 2][s] = v.z; Kt[d0 + 3][s] = v.w;
    }
    __syncthreads();
    int q = tid >> 2;
    int sl = tid & 3;
    float acc[20];
    #pragma unroll
    for (int j = 0; j < 20; j++) acc[j] = 0.f;
    #pragma unroll 4
    for (int d = 0; d < 64; d++) {
        float qv = Qs[d][q];
        #pragma unroll
        for (int j = 0; j < 20; j++) {
            int s = sl + j * 4;
            if (s < Sv) acc[j] += qv * Kt[d][s];
        }
    }
    size_t rbase = ((size_t)bh * Nv + qt * 64 + q) * Sv;
    #pragma unroll
    for (int j = 0; j < 20; j++) {
        int s = sl + j * 4;
        if (s < Sv) {
            float v = mask[b * Sv + s] ? -INFINITY : acc[j] * ATT_SCALE;
            cs[rbase + s] = v;
        }
    }
}

// ca = softmax(cs) @ Vc -> bf16 hi/lo split. Softmax done in-smem on the
// At[s][q] tile (4 threads per q-row over 77 keys).
__global__ __launch_bounds__(256) void ca_av_kernel(
    const float* __restrict__ cs, const float* __restrict__ kvc,
    __nv_bfloat16* __restrict__ hi, __nv_bfloat16* __restrict__ lo) {
    __shared__ float At[Sv][68];
    __shared__ float Vs[Sv][68];
    __shared__ float pbuf[64][4];
    int qt = blockIdx.x, bh = blockIdx.y;
    int b = bh >> 4, h = bh & 15;
    int tid = threadIdx.x;
    for (int idx = tid; idx < 64 * Sv; idx += 256) {
        int q = idx / Sv, s = idx % Sv;
        At[s][q] = cs[((size_t)bh * Nv + qt * 64 + q) * Sv + s];
    }
    for (int idx = tid; idx < Sv * 16; idx += 256) {
        int s = idx >> 4, d0 = (idx & 15) * 4;
        *(float4*)&Vs[s][d0] =
            *(const float4*)(kvc + ((size_t)(b * Sv + s) * 2 + 1) * Dv + h * HDv + d0);
    }
    __syncthreads();

    // in-smem softmax over s (77) for each of the 64 q-rows; 4 threads/row
    {
        int q = tid >> 2, part = tid & 3;
        float m = -INFINITY;
        for (int s = part; s < Sv; s += 4) m = fmaxf(m, At[s][q]);
        pbuf[q][part] = m;
        __syncthreads();
        float rm = fmaxf(fmaxf(pbuf[q][0], pbuf[q][1]),
                         fmaxf(pbuf[q][2], pbuf[q][3]));
        __syncthreads();
        float sum = 0.f;
        for (int s = part; s < Sv; s += 4) sum += __expf(At[s][q] - rm);
        pbuf[q][part] = sum;
        __syncthreads();
        float rinv = 1.f / (pbuf[q][0] + pbuf[q][1] + pbuf[q][2] + pbuf[q][3]);
        for (int s = part; s < Sv; s += 4)
            At[s][q] = __expf(At[s][q] - rm) * rinv;
        __syncthreads();
    }

    int tx = tid & 15, ty = tid >> 4;
    float acc[4][4] = {};
    #pragma unroll 7
    for (int s = 0; s < Sv; s++) {
        float4 a4 = *(const float4*)&At[s][ty * 4];
        float4 v4 = *(const float4*)&Vs[s][tx * 4];
        float aa[4] = {a4.x, a4.y, a4.z, a4.w};
        float vv[4] = {v4.x, v4.y, v4.z, v4.w};
        #pragma unroll
        for (int i = 0; i < 4; i++)
            #pragma unroll
            for (int j = 0; j < 4; j++) acc[i][j] += aa[i] * vv[j];
    }
    #pragma unroll
    for (int i = 0; i < 4; i++) {
        int q = qt * 64 + ty * 4 + i;
        size_t off = (size_t)(b * Nv + q) * Dv + h * HDv + tx * 4;
        __nv_bfloat16 h0, h1, h2, h3, l0, l1, l2, l3;
        bf_split(acc[i][0], h0, l0); bf_split(acc[i][1], h1, l1);
        bf_split(acc[i][2], h2, l2); bf_split(acc[i][3], h3, l3);
        *(__nv_bfloat162*)(hi + off)     = __nv_bfloat162(h0, h1);
        *(__nv_bfloat162*)(hi + off + 2) = __nv_bfloat162(h2, h3);
        *(__nv_bfloat162*)(lo + off)     = __nv_bfloat162(l0, l1);
        *(__nv_bfloat162*)(lo + off + 2) = __nv_bfloat162(l2, l3);
    }
}

// -------------------------- launch -----------------------------------------
extern "C" void kernel_launch(void* const* d_in, const int* in_sizes, int n_in,
                              void* d_out, int out_size) {
    const float* x      = (const float*)d_in[0];
    const float* t_emb  = (const float*)d_in[1];
    const float* ctx    = (const float*)d_in[2];
    const char*  cmask  = (const char*)d_in[3];
    const float* ada_w  = (const float*)d_in[4];
    const float* ada_b  = (const float*)d_in[5];
    const float* qkv_w  = (const float*)d_in[6];
    const float* qkv_b  = (const float*)d_in[7];
    const float* sa_w   = (const float*)d_in[8];
    const float* sa_b   = (const float*)d_in[9];
    const float* q_w    = (const float*)d_in[10];
    const float* q_b    = (const float*)d_in[11];
    const float* kv_w   = (const float*)d_in[12];
    const float* kv_b   = (const float*)d_in[13];
    const float* ca_w   = (const float*)d_in[14];
    const float* ca_b   = (const float*)d_in[15];
    const float* fc1_w  = (const float*)d_in[16];
    const float* fc1_b  = (const float*)d_in[17];
    const float* fc2_w  = (const float*)d_in[18];
    const float* fc2_b  = (const float*)d_in[19];
    float* out = (float*)d_out;

    float *ts, *mod, *qkv, *sc, *x1, *qc, *kvc, *cs, *x2, *hb;
    __nv_bfloat16 *whi, *wlo, *ahi, *alo;
    cudaGetSymbolAddress((void**)&ts,  g_ts);
    cudaGetSymbolAddress((void**)&mod, g_mod);
    cudaGetSymbolAddress((void**)&qkv, g_qkv);
    cudaGetSymbolAddress((void**)&sc,  g_scores);
    cudaGetSymbolAddress((void**)&x1,  g_x1);
    cudaGetSymbolAddress((void**)&qc,  g_qc);
    cudaGetSymbolAddress((void**)&kvc, g_kvc);
    cudaGetSymbolAddress((void**)&cs,  g_cs);
    cudaGetSymbolAddress((void**)&x2,  g_x2);
    cudaGetSymbolAddress((void**)&hb,  g_h);
    cudaGetSymbolAddress((void**)&whi, g_whi);
    cudaGetSymbolAddress((void**)&wlo, g_wlo);
    cudaGetSymbolAddress((void**)&ahi, g_ahi);
    cudaGetSymbolAddress((void**)&alo, g_alo);

    // fc1 bf16 hi/lo planes inside g_h (2 * WTOT bf16 = 64 MB = sizeof g_h)
    __nv_bfloat16* hbh = (__nv_bfloat16*)hb;
    __nv_bfloat16* hbl = hbh + WTOT;

    cudaFuncSetAttribute(gemm_mma, cudaFuncAttributeMaxDynamicSharedMemorySize,
                         GMM_SMEM);

    dim3 t328(32, 8);
    transp_split_kernel<<<dim3(3 * Dv / 32, Dv / 32), t328>>>(qkv_w, whi + OFF_QKV, wlo + OFF_QKV, Dv, 3 * Dv);
    transp_split_kernel<<<dim3(Dv / 32, Dv / 32), t328>>>(sa_w,  whi + OFF_SAP, wlo + OFF_SAP, Dv, Dv);
    transp_split_kernel<<<dim3(Dv / 32, Dv / 32), t328>>>(q_w,   whi + OFF_QW,  wlo + OFF_QW,  Dv, Dv);
    transp_split_kernel<<<dim3(2 * Dv / 32, Dv / 32), t328>>>(kv_w, whi + OFF_KV, wlo + OFF_KV, Dv, 2 * Dv);
    transp_split_kernel<<<dim3(Dv / 32, Dv / 32), t328>>>(ca_w,  whi + OFF_CAP, wlo + OFF_CAP, Dv, Dv);
    transp_split_kernel<<<dim3(DFv / 32, Dv / 32), t328>>>(fc1_w, whi + OFF_FC1, wlo + OFF_FC1, Dv, DFv);
    transp_split_kernel<<<dim3(Dv / 32, DFv / 32), t328>>>(fc2_w, whi + OFF_FC2, wlo + OFF_FC2, DFv, Dv);

    // 1. modulation
    silu_kernel<<<16, 256>>>(t_emb, ts);
    mod_gemm_kernel<<<24, 256>>>(ts, ada_w, ada_b, mod);

    // 2. self-attention branch (softmax fused into attn_v)
    ln_split_kernel<<<Bv * Nv, 256>>>(x, mod, 0, ahi, alo);
    gemm_mma<<<dim3(24, 32), 256, GMM_SMEM>>>(ahi, alo, whi + OFF_QKV, wlo + OFF_QKV,
        qkv_b, qkv, Bv * Nv, 3 * Dv, Dv, EPI_NONE, nullptr, nullptr, -1, nullptr, nullptr);
    sa_scores_kernel<<<dim3(16, 64), 256>>>(qkv, sc);
    attn_v_kernel<<<dim3(16, 64), 256>>>(sc, qkv, ahi, alo);
    gemm_mma<<<dim3(8, 32), 256, GMM_SMEM>>>(ahi, alo, whi + OFF_SAP, wlo + OFF_SAP,
        sa_b, x1, Bv * Nv, Dv, Dv, EPI_NONE, x, mod, 2, nullptr, nullptr);

    // 3. cross-attention branch (softmax fused into ca_av)
    ln_split_kernel<<<Bv * Nv, 256>>>(x1, mod, -1, ahi, alo);
    gemm_mma<<<dim3(8, 32), 256, GMM_SMEM>>>(ahi, alo, whi + OFF_QW, wlo + OFF_QW,
        q_b, qc, Bv * Nv, Dv, Dv, EPI_NONE, nullptr, nullptr, -1, nullptr, nullptr);
    split_kernel<<<308, 256>>>(ctx, ahi, alo, Bv * Sv * Dv / 4);
    gemm_mma<<<dim3(16, 3), 256, GMM_SMEM>>>(ahi, alo, whi + OFF_KV, wlo + OFF_KV,
        kv_b, kvc, Bv * Sv, 2 * Dv, Dv, EPI_NONE, nullptr, nullptr, -1, nullptr, nullptr);
    ca_scores_kernel<<<dim3(16, 64), 256>>>(qc, kvc, cmask, cs);
    ca_av_kernel<<<dim3(16, 64), 256>>>(cs, kvc, ahi, alo);
    gemm_mma<<<dim3(8, 32), 256, GMM_SMEM>>>(ahi, alo, whi + OFF_CAP, wlo + OFF_CAP,
        ca_b, x2, Bv * Nv, Dv, Dv, EPI_NONE, x1, nullptr, -1, nullptr, nullptr);

    // 4. MLP branch
    ln_split_kernel<<<Bv * Nv, 256>>>(x2, mod, 3, ahi, alo);
    gemm_mma<<<dim3(32, 32), 256, GMM_SMEM>>>(ahi, alo, whi + OFF_FC1, wlo + OFF_FC1,
        fc1_b, nullptr, Bv * Nv, DFv, Dv, EPI_GELU_SPLIT, nullptr, nullptr, -1, hbh, hbl);
    gemm_mma<<<dim3(8, 32), 256, GMM_SMEM>>>(hbh, hbl, whi + OFF_FC2, wlo + OFF_FC2,
        fc2_b, out, Bv * Nv, Dv, DFv, EPI_NONE, x2, mod, 5, nullptr, nullptr);
}